// round 8
// baseline (speedup 1.0000x reference)
#include <cuda_runtime.h>
#include <math_constants.h>

// HPSS: S (2,2,1025,1024) fp32.
//   harm = median_31 along W (zero pad), perc = median_31 along H (zero pad)
//   mask_h = harm^2/(harm^2+perc^2), mask_p = perc^2/(harm^2+perc^2)
//   out[0:N) = S*mask_h ; out[N:2N) = S*mask_p
//
// R8: R6 algorithm (shared sorted base + incrementally maintained sorted
// private set + rank select) with:
//   - NO min-blocks occupancy cap (R7's cap of 72 regs caused spills).
//   - parallel depth-2 sorted-insert (out[j]=max(min(w[j],u),w[j-1]))
//     replacing the depth-28 serial carry chain -> latency-bound -> not.
//   - Batcher odd-even mergesort (63 CE) for the per-run sorts.

#define IMG_H 1025
#define IMG_W 1024
#define N_IMG 4
#define HALO  15

#define TILE_W 64
#define TILE_H 32
#define PATCH_H (TILE_H + 2 * HALO)   // 62
#define PATCH_W (TILE_W + 2 * HALO)   // 94
#define PITCH   (PATCH_W + 1)         // 95 (odd -> conflict-free column access)
#define NTHREADS 128

__device__ __forceinline__ void ce(float& a, float& b) {
    float mn = fminf(a, b);
    float mx = fmaxf(a, b);
    a = mn; b = mx;
}

// Batcher odd-even mergesort, n=16: 63 compare-exchanges.
__device__ __forceinline__ void sort16(float v[16]) {
    const int n = 16;
#pragma unroll
    for (int p = 1; p < n; p <<= 1) {
#pragma unroll
        for (int k = p; k >= 1; k >>= 1) {
#pragma unroll
            for (int j = k % p; j + k < n; j += 2 * k) {
#pragma unroll
                for (int i = 0; i < k; i++) {
                    if (i + j + k < n) {
                        if ((i + j) / (2 * p) == (i + j + k) / (2 * p))
                            ce(v[i + j], v[i + j + k]);
                    }
                }
            }
        }
    }
}

// Rank-15 (0-indexed; 16th smallest) of sorted P[0..14] u sorted b[0..15].
__device__ __forceinline__ float sel16th(const float P[16], const float b[16]) {
    float c[16];
    c[0] = b[15];
#pragma unroll
    for (int j = 1; j <= 15; j++) c[j] = fmaxf(P[j - 1], b[15 - j]);
#pragma unroll
    for (int s = 8; s >= 1; s >>= 1)
#pragma unroll
        for (int j = 0; j < s; j++) c[j] = fminf(c[j], c[j + s]);
    return c[0];
}

// Replace value v (present in sorted P[0..14]) with u, restoring sorted order.
// Delete: parallel shift-select (depth 1). Insert: parallel merge (depth 2):
//   P[0]=min(w[0],u); P[j]=max(min(w[j],u), w[j-1]); P[14]=max(w[13],u).
// P[15] stays +INF.
__device__ __forceinline__ void replace_sorted(float P[16], float v, float u) {
    float w[14];
#pragma unroll
    for (int j = 0; j < 14; j++)
        w[j] = (P[j] < v) ? P[j] : P[j + 1];   // delete first occurrence of v
    P[0] = fminf(w[0], u);
#pragma unroll
    for (int j = 1; j < 14; j++)
        P[j] = fmaxf(fminf(w[j], u), w[j - 1]);
    P[14] = fmaxf(w[13], u);
}

__global__ __launch_bounds__(NTHREADS)
void hpss_kernel(const float* __restrict__ S, float* __restrict__ out) {
    __shared__ float patch[PATCH_H][PITCH];
    __shared__ float harm[TILE_H][TILE_W + 1];

    const int bx  = blockIdx.x * TILE_W;
    const int by  = blockIdx.y * TILE_H;
    const int img = blockIdx.z;
    const float* __restrict__ Simg = S + (size_t)img * IMG_H * IMG_W;

    const int tid = threadIdx.x;

    // Cooperative patch load with zero padding.
#pragma unroll 4
    for (int idx = tid; idx < PATCH_H * PATCH_W; idx += NTHREADS) {
        int r = idx / PATCH_W;
        int c = idx - r * PATCH_W;
        int gh = by + r - HALO;
        int gw = bx + c - HALO;
        float val = 0.0f;
        if (gh >= 0 && gh < IMG_H && gw >= 0 && gw < IMG_W)
            val = Simg[gh * IMG_W + gw];
        patch[r][c] = val;
    }
    __syncthreads();

    // ---- Phase A: horizontal medians (harm); thread owns a 16-wide row run.
    {
        const int row = tid & 31;       // 0..31
        const int g   = tid >> 5;       // 0..3 -> cols g*16..g*16+15
        const int c0  = g * 16;
        const float* __restrict__ q = &patch[row + HALO][c0];

        float b[16], P[16];
#pragma unroll
        for (int j = 0; j < 16; j++) b[j] = q[15 + j];
        sort16(b);

#pragma unroll
        for (int j = 0; j < 15; j++) P[j] = q[j];   // L = positions 0..14
        P[15] = CUDART_INF_F;
        sort16(P);                                   // INF stays at P[15]

#pragma unroll
        for (int i = 0; i < 16; i++) {
            if (i > 0)
                replace_sorted(P, q[i - 1], q[31 + i - 1]); // drop L[i-1], add R[i-1]
            harm[row][c0 + i] = sel16th(P, b);
        }
    }
    __syncthreads();

    // ---- Phase B: vertical medians (perc); thread owns a 16-tall col run;
    //      combine with harm + S, write both output planes.
    {
        const int col = tid & 63;       // 0..63
        const int gy  = tid >> 6;       // 0..1 -> rows gy*16..gy*16+15
        const int r0  = gy * 16;
        const float* __restrict__ q = &patch[r0][col + HALO];

        float b[16], P[16];
#pragma unroll
        for (int j = 0; j < 16; j++) b[j] = q[(15 + j) * PITCH];
        sort16(b);

#pragma unroll
        for (int j = 0; j < 15; j++) P[j] = q[j * PITCH];
        P[15] = CUDART_INF_F;
        sort16(P);

        const size_t plane = (size_t)N_IMG * IMG_H * IMG_W;

#pragma unroll
        for (int i = 0; i < 16; i++) {
            if (i > 0)
                replace_sorted(P, q[(i - 1) * PITCH], q[(31 + i - 1) * PITCH]);
            float p = sel16th(P, b);

            int h_local = r0 + i;
            int gh = by + h_local;
            if (gh < IMG_H) {
                float hmed = harm[h_local][col];
                float s    = patch[h_local + HALO][col + HALO];

                float hh = hmed * hmed;
                float pp = p * p;
                float inv = 1.0f / (hh + pp);

                size_t o = (size_t)img * (IMG_H * IMG_W) + (size_t)gh * IMG_W
                         + (bx + col);
                out[o]         = s * (hh * inv);
                out[o + plane] = s * (pp * inv);
            }
        }
    }
}

extern "C" void kernel_launch(void* const* d_in, const int* in_sizes, int n_in,
                              void* d_out, int out_size) {
    const float* S = (const float*)d_in[0];
    float* out = (float*)d_out;
    (void)in_sizes; (void)n_in; (void)out_size;

    dim3 block(NTHREADS);
    dim3 grid(IMG_W / TILE_W, (IMG_H + TILE_H - 1) / TILE_H, N_IMG);
    hpss_kernel<<<grid, block>>>(S, out);
}

// round 10
// speedup vs baseline: 1.2579x; 1.2579x over previous
#include <cuda_runtime.h>
#include <math_constants.h>

// HPSS: S (2,2,1025,1024) fp32.
//   harm = median_31 along W (zero pad), perc = median_31 along H (zero pad)
//   mask_h = harm^2/(harm^2+perc^2), mask_p = perc^2/(harm^2+perc^2)
//   out[0:N) = S*mask_h ; out[N:2N) = S*mask_p
//
// R9: exact R6 structure (bitonic sort16 — fully static register indexing;
// NO launch_bounds cap) with ONE change: the sorted-insert inside
// replace_sorted is the depth-2 parallel form instead of the depth-28
// serial carry chain. R7/R8 regressions traced to Batcher sort's
// partially-dynamic indexing demoting register arrays to local memory.

#define IMG_H 1025
#define IMG_W 1024
#define N_IMG 4
#define HALO  15

#define TILE_W 64
#define TILE_H 32
#define PATCH_H (TILE_H + 2 * HALO)   // 62
#define PATCH_W (TILE_W + 2 * HALO)   // 94
#define PITCH   (PATCH_W + 1)         // 95 (odd -> conflict-free column access)
#define NTHREADS 128

// Bitonic sort, n=16: 80 CE, every array index a literal constant after
// unrolling (this is what keeps v[] in registers — do not "optimize").
__device__ __forceinline__ void sort16(float v[16]) {
#pragma unroll
    for (int k = 2; k <= 16; k <<= 1) {
#pragma unroll
        for (int j = k >> 1; j > 0; j >>= 1) {
#pragma unroll
            for (int i = 0; i < 16; i++) {
                int l = i ^ j;
                if (l > i) {
                    float a = v[i], b = v[l];
                    float mn = fminf(a, b);
                    float mx = fmaxf(a, b);
                    if ((i & k) == 0) { v[i] = mn; v[l] = mx; }
                    else              { v[i] = mx; v[l] = mn; }
                }
            }
        }
    }
}

// Rank-15 (0-indexed; 16th smallest) of sorted P[0..14] u sorted b[0..15].
__device__ __forceinline__ float sel16th(const float P[16], const float b[16]) {
    float c[16];
    c[0] = b[15];
#pragma unroll
    for (int j = 1; j <= 15; j++) c[j] = fmaxf(P[j - 1], b[15 - j]);
#pragma unroll
    for (int s = 8; s >= 1; s >>= 1)
#pragma unroll
        for (int j = 0; j < s; j++) c[j] = fminf(c[j], c[j + s]);
    return c[0];
}

// Replace value v (present in sorted P[0..14]) with u, restoring sorted order.
// Delete: parallel shift-select (depth 1). Insert: parallel merge (depth 2):
//   P[0]=min(w[0],u); P[j]=max(min(w[j],u), w[j-1]); P[14]=max(w[13],u).
// P[15] stays +INF.
__device__ __forceinline__ void replace_sorted(float P[16], float v, float u) {
    float w[14];
#pragma unroll
    for (int j = 0; j < 14; j++)
        w[j] = (P[j] < v) ? P[j] : P[j + 1];   // delete first occurrence of v
    P[0] = fminf(w[0], u);
#pragma unroll
    for (int j = 1; j < 14; j++)
        P[j] = fmaxf(fminf(w[j], u), w[j - 1]);
    P[14] = fmaxf(w[13], u);
}

__global__ __launch_bounds__(NTHREADS)
void hpss_kernel(const float* __restrict__ S, float* __restrict__ out) {
    __shared__ float patch[PATCH_H][PITCH];
    __shared__ float harm[TILE_H][TILE_W + 1];

    const int bx  = blockIdx.x * TILE_W;
    const int by  = blockIdx.y * TILE_H;
    const int img = blockIdx.z;
    const float* __restrict__ Simg = S + (size_t)img * IMG_H * IMG_W;

    const int tid = threadIdx.x;

    // Cooperative patch load with zero padding.
#pragma unroll 4
    for (int idx = tid; idx < PATCH_H * PATCH_W; idx += NTHREADS) {
        int r = idx / PATCH_W;
        int c = idx - r * PATCH_W;
        int gh = by + r - HALO;
        int gw = bx + c - HALO;
        float val = 0.0f;
        if (gh >= 0 && gh < IMG_H && gw >= 0 && gw < IMG_W)
            val = Simg[gh * IMG_W + gw];
        patch[r][c] = val;
    }
    __syncthreads();

    // ---- Phase A: horizontal medians (harm); thread owns a 16-wide row run.
    {
        const int row = tid & 31;       // 0..31
        const int g   = tid >> 5;       // 0..3 -> cols g*16..g*16+15
        const int c0  = g * 16;
        const float* __restrict__ q = &patch[row + HALO][c0];

        float b[16], P[16];
#pragma unroll
        for (int j = 0; j < 16; j++) b[j] = q[15 + j];
        sort16(b);

#pragma unroll
        for (int j = 0; j < 15; j++) P[j] = q[j];   // L = positions 0..14
        P[15] = CUDART_INF_F;
        sort16(P);                                   // INF stays at P[15]

#pragma unroll
        for (int i = 0; i < 16; i++) {
            if (i > 0)
                replace_sorted(P, q[i - 1], q[31 + i - 1]); // drop L[i-1], add R[i-1]
            harm[row][c0 + i] = sel16th(P, b);
        }
    }
    __syncthreads();

    // ---- Phase B: vertical medians (perc); thread owns a 16-tall col run;
    //      combine with harm + S, write both output planes.
    {
        const int col = tid & 63;       // 0..63
        const int gy  = tid >> 6;       // 0..1 -> rows gy*16..gy*16+15
        const int r0  = gy * 16;
        const float* __restrict__ q = &patch[r0][col + HALO];

        float b[16], P[16];
#pragma unroll
        for (int j = 0; j < 16; j++) b[j] = q[(15 + j) * PITCH];
        sort16(b);

#pragma unroll
        for (int j = 0; j < 15; j++) P[j] = q[j * PITCH];
        P[15] = CUDART_INF_F;
        sort16(P);

        const size_t plane = (size_t)N_IMG * IMG_H * IMG_W;

#pragma unroll
        for (int i = 0; i < 16; i++) {
            if (i > 0)
                replace_sorted(P, q[(i - 1) * PITCH], q[(31 + i - 1) * PITCH]);
            float p = sel16th(P, b);

            int h_local = r0 + i;
            int gh = by + h_local;
            if (gh < IMG_H) {
                float hmed = harm[h_local][col];
                float s    = patch[h_local + HALO][col + HALO];

                float hh = hmed * hmed;
                float pp = p * p;
                float inv = 1.0f / (hh + pp);

                size_t o = (size_t)img * (IMG_H * IMG_W) + (size_t)gh * IMG_W
                         + (bx + col);
                out[o]         = s * (hh * inv);
                out[o + plane] = s * (pp * inv);
            }
        }
    }
}

extern "C" void kernel_launch(void* const* d_in, const int* in_sizes, int n_in,
                              void* d_out, int out_size) {
    const float* S = (const float*)d_in[0];
    float* out = (float*)d_out;
    (void)in_sizes; (void)n_in; (void)out_size;

    dim3 block(NTHREADS);
    dim3 grid(IMG_W / TILE_W, (IMG_H + TILE_H - 1) / TILE_H, N_IMG);
    hpss_kernel<<<grid, block>>>(S, out);
}